// round 9
// baseline (speedup 1.0000x reference)
#include <cuda_runtime.h>
#include <cuda_fp16.h>

// ---------------------------------------------------------------------------
// Exact-rank 5x5 median filter, fp32 in/out, symmetric (reflect) padding.
//   * packed fp16 comparators (HMNMX2): lanes = 2 image planes
//   * vertical sliding strip per thread, ring of 5 sorted rows
//   * software prefetch: next row's loads issued one full iteration early
//   * explicit partial-rank column networks (64 ops)
//   * doubly-sorted matrix pruning: median(25) = rank-7 of 13 candidates
//   * x4096 fp32 pre-scale avoids fp16 denormals; /4096 on output (exact pow2)
//   * __launch_bounds__(128, 8): force <=64 regs -> 8 CTAs/SM (occ 50%)
// ---------------------------------------------------------------------------

typedef __half2 h2;

__device__ __forceinline__ void cex(h2& a, h2& b) {
    h2 mn = __hmin2(a, b);
    b = __hmax2(a, b);
    a = mn;
}

// symmetric reflect for pad<=2:  -1->0, -2->1, N->N-1, N+1->N-2
__device__ __forceinline__ int refl(int i, int n) {
    i = (i < 0) ? (-1 - i) : i;
    i = (i >= n) ? (2 * n - 1 - i) : i;
    return i;
}

constexpr int IMG_H   = 512;
constexpr int IMG_W   = 512;
constexpr int PLANES  = 16 * 3;           // 48
constexpr int PAIRS   = PLANES / 2;       // 24 packed plane-pairs
constexpr int TROWS   = 16;               // output rows per thread
constexpr int STRIPS  = IMG_H / TROWS;    // 32
constexpr int PSTRIDE = IMG_H * IMG_W;

constexpr float SCALE     = 4096.0f;
constexpr float INV_SCALE = 1.0f / 4096.0f;

__device__ __forceinline__ void load_raw(const float* __restrict__ row,
                                         int xm2, int xm1, int x, int xp1, int xp2,
                                         float a[5], float b[5]) {
    a[0] = __ldg(row + xm2); a[1] = __ldg(row + xm1); a[2] = __ldg(row + x);
    a[3] = __ldg(row + xp1); a[4] = __ldg(row + xp2);
    const float* rb = row + PSTRIDE;
    b[0] = __ldg(rb + xm2); b[1] = __ldg(rb + xm1); b[2] = __ldg(rb + x);
    b[3] = __ldg(rb + xp1); b[4] = __ldg(rb + xp2);
}

// scale + pack + optimal 9-CE sort5
__device__ __forceinline__ void cvt_sort(const float a[5], const float b[5], h2 o[5]) {
    #pragma unroll
    for (int k = 0; k < 5; k++)
        o[k] = __floats2half2_rn(a[k] * SCALE, b[k] * SCALE);
    cex(o[0], o[1]); cex(o[3], o[4]); cex(o[2], o[4]); cex(o[2], o[3]);
    cex(o[0], o[3]); cex(o[0], o[2]); cex(o[1], o[4]); cex(o[1], o[3]); cex(o[1], o[2]);
}

// rank-7 of the 13 pruned candidates (verified R4/R5/R6)
__device__ __forceinline__ h2 sel13(h2 a3, h2 a4, h2 b2, h2 b3, h2 b4,
                                    h2 c1, h2 c2, h2 c3,
                                    h2 d0, h2 d1, h2 d2, h2 e0, h2 e1) {
    // U = merge((d0,e0),(c1,d1,e1)) -> sorted 5
    h2 s0 = __hmin2(d0, c1), t0 = __hmax2(d0, c1);
    h2 v1 = __hmin2(t0, e1), v2 = __hmax2(t0, e1);
    h2 w0 = __hmin2(e0, d1), w1 = __hmax2(e0, d1);
    h2 U0 = s0;
    h2 U1 = __hmin2(v1, w0), U2 = __hmax2(v1, w0);
    h2 U3 = __hmin2(v2, w1), U4 = __hmax2(v2, w1);

    // V = merge((a3,b3,c3),(a4,b4)) -> sorted 5
    h2 m0 = __hmin2(a3, a4), h0 = __hmax2(a3, a4);
    h2 o1 = __hmin2(h0, c3), o2 = __hmax2(h0, c3);
    h2 p0 = __hmin2(b3, b4), p1 = __hmax2(b3, b4);
    h2 V0 = m0;
    h2 V1 = __hmin2(o1, p0), V2 = __hmax2(o1, p0);
    h2 V3 = __hmin2(o2, p1), V4 = __hmax2(o2, p1);

    // W = merge(U(5), (b2,c2,d2)) -> sorted 8, lanes W1..W6 only
    h2 hh  = __hmax2(U0, b2);
    h2 oo1 = __hmin2(hh, U4), oo2 = __hmax2(hh, U4);
    h2 qq0 = __hmin2(U2, d2), qq1 = __hmax2(U2, d2);
    h2 O1 = __hmin2(oo1, qq0), O2 = __hmax2(oo1, qq0);
    h2 O3 = __hmin2(oo2, qq1);
    h2 m2 = __hmin2(U1, c2), h2v = __hmax2(U1, c2);
    h2 E0 = m2;
    h2 E1 = __hmin2(h2v, U3), E2 = __hmax2(h2v, U3);
    h2 W1 = __hmin2(O1, E0), W2 = __hmax2(O1, E0);
    h2 W3 = __hmin2(O2, E1), W4 = __hmax2(O2, E1);
    h2 W5 = __hmin2(O3, E2), W6 = __hmax2(O3, E2);

    // rank-7 of union(W sorted 8, V sorted 5)
    h2 med = W6;
    med = __hmin2(med, __hmax2(W1, V4));
    med = __hmin2(med, __hmax2(W2, V3));
    med = __hmin2(med, __hmax2(W3, V2));
    med = __hmin2(med, __hmax2(W4, V1));
    med = __hmin2(med, __hmax2(W5, V0));
    return med;
}

// median of the 5 sorted rows r[0..4] via doubly-sorted-matrix pruning with
// explicit partial-rank column networks.
__device__ __forceinline__ h2 median25(const h2 r[5][5]) {
    // ---- col 0: top-2 -> a3,a4 ----
    h2 a3, a4;
    {
        h2 p = r[0][0], q = r[1][0], rr = r[2][0], ss = r[3][0], e = r[4][0];
        h2 h1 = __hmax2(p, q),  l1 = __hmin2(p, q);
        h2 hB = __hmax2(rr, ss), lB = __hmin2(rr, ss);
        h2 t4 = __hmax2(h1, hB);
        h2 t3 = __hmax2(__hmin2(h1, hB), __hmax2(l1, lB));
        a4 = __hmax2(e, t4);
        a3 = __hmax2(__hmin2(e, t4), t3);
    }
    // ---- col 4: bottom-2 -> e0,e1 ----
    h2 e0, e1;
    {
        h2 p = r[0][4], q = r[1][4], rr = r[2][4], ss = r[3][4], e = r[4][4];
        h2 h1 = __hmax2(p, q),  l1 = __hmin2(p, q);
        h2 hB = __hmax2(rr, ss), lB = __hmin2(rr, ss);
        h2 t0 = __hmin2(l1, lB);
        h2 t1 = __hmin2(__hmax2(l1, lB), __hmin2(h1, hB));
        e0 = __hmin2(e, t0);
        e1 = __hmin2(__hmax2(e, t0), t1);
    }
    // ---- col 1: top-3 -> b2,b3,b4 ----
    h2 b2, b3, b4;
    {
        h2 p = r[0][1], q = r[1][1], rr = r[2][1], ss = r[3][1], e = r[4][1];
        h2 lo1 = __hmin2(p, q),  hi1 = __hmax2(p, q);
        h2 lo2 = __hmin2(rr, ss), hi2 = __hmax2(rr, ss);
        h2 s3 = __hmax2(hi1, hi2);
        h2 bm = __hmin2(hi1, hi2), cm = __hmax2(lo1, lo2);
        h2 s1 = __hmin2(bm, cm), s2 = __hmax2(bm, cm);
        b4 = __hmax2(e, s3);
        h2 m = __hmin2(e, s3);
        b3 = __hmax2(m, s2);
        h2 m2 = __hmin2(m, s2);
        b2 = __hmax2(m2, s1);
    }
    // ---- col 3: bottom-3 -> d0,d1,d2 ----
    h2 d0, d1, d2;
    {
        h2 p = r[0][3], q = r[1][3], rr = r[2][3], ss = r[3][3], e = r[4][3];
        h2 lo1 = __hmin2(p, q),  hi1 = __hmax2(p, q);
        h2 lo2 = __hmin2(rr, ss), hi2 = __hmax2(rr, ss);
        h2 s0 = __hmin2(lo1, lo2);
        h2 cm = __hmax2(lo1, lo2), bm = __hmin2(hi1, hi2);
        h2 s1 = __hmin2(cm, bm), s2 = __hmax2(cm, bm);
        d0 = __hmin2(e, s0);
        h2 m = __hmax2(e, s0);
        d1 = __hmin2(m, s1);
        h2 m2 = __hmax2(m, s1);
        d2 = __hmin2(m2, s2);
    }
    // ---- col 2: middle-3 -> c1,c2,c3 ----
    h2 c1, c2, c3;
    {
        h2 s0 = r[0][2], s1 = r[1][2], s2 = r[2][2], s3 = r[3][2], e = r[4][2];
        cex(s0, s1); cex(s2, s3); cex(s0, s2); cex(s1, s3); cex(s1, s2);   // sort4
        h2 u = __hmax2(e, s0);
        c1 = __hmin2(u, s1); u = __hmax2(u, s1);
        c2 = __hmin2(u, s2); u = __hmax2(u, s2);
        c3 = __hmin2(u, s3);
    }
    return sel13(a3, a4, b2, b3, b4, c1, c2, c3, d0, d1, d2, e0, e1);
}

__global__ void __launch_bounds__(128, 8)
median5x5_kernel(const float* __restrict__ src, float* __restrict__ dst) {
    const int tid   = blockIdx.x * blockDim.x + threadIdx.x;
    const int x     = tid & (IMG_W - 1);
    const int rest  = tid >> 9;                 // / 512
    const int strip = rest & (STRIPS - 1);      // % 32
    const int pair  = rest >> 5;                // / 32
    if (pair >= PAIRS) return;

    const float* sA = src + (size_t)(2 * pair) * PSTRIDE;
    float*       dA = dst + (size_t)(2 * pair) * PSTRIDE;

    const int xm2 = refl(x - 2, IMG_W);
    const int xm1 = refl(x - 1, IMG_W);
    const int xp1 = refl(x + 1, IMG_W);
    const int xp2 = refl(x + 2, IMG_W);
    const int y0  = strip * TROWS;

    // Ring of 5 sorted rows. Row (y0+t+2) lands in slot (t+4)%5.
    h2 r[5][5];

    #pragma unroll
    for (int i = 0; i < 4; i++) {               // rows y0-2 .. y0+1 -> slots 0..3
        float a[5], b[5];
        const int yy = refl(y0 - 2 + i, IMG_H);
        load_raw(sA + yy * IMG_W, xm2, xm1, x, xp1, xp2, a, b);
        cvt_sort(a, b, r[i]);
    }

    // prefetch row y0+2 (consumed in iter t=0)
    float rawA[5], rawB[5];
    load_raw(sA + refl(y0 + 2, IMG_H) * IMG_W, xm2, xm1, x, xp1, xp2, rawA, rawB);

    #pragma unroll
    for (int t = 0; t < TROWS; t++) {
        // 1) issue next row's loads FIRST — they complete under the network
        float nA[5], nB[5];
        load_raw(sA + refl(y0 + t + 3, IMG_H) * IMG_W, xm2, xm1, x, xp1, xp2, nA, nB);

        // 2) consume prefetched row into the ring (loads landed last iter)
        cvt_sort(rawA, rawB, r[(t + 4) % 5]);

        // 3) big comparator network (overlaps the in-flight loads)
        h2 med = median25(r);

        const float mA = __low2float(med)  * INV_SCALE;
        const float mB = __high2float(med) * INV_SCALE;
        dA[(y0 + t) * IMG_W + x]           = mA;
        dA[(y0 + t) * IMG_W + x + PSTRIDE] = mB;

        #pragma unroll
        for (int k = 0; k < 5; k++) { rawA[k] = nA[k]; rawB[k] = nB[k]; }
    }
}

extern "C" void kernel_launch(void* const* d_in, const int* in_sizes, int n_in,
                              void* d_out, int out_size) {
    (void)in_sizes; (void)n_in; (void)out_size;
    const float* src = (const float*)d_in[0];
    float*       dst = (float*)d_out;

    const int total_threads = PAIRS * IMG_W * STRIPS;   // 393216
    const int block = 128;
    const int grid  = total_threads / block;            // 3072
    median5x5_kernel<<<grid, block>>>(src, dst);
}

// round 10
// speedup vs baseline: 1.0947x; 1.0947x over previous
#include <cuda_runtime.h>
#include <cuda_fp16.h>

// ---------------------------------------------------------------------------
// Exact-rank 5x5 median filter, fp32 in/out, symmetric (reflect) padding.
//   * packed fp16 comparators (HMNMX2): lanes = 2 image planes
//   * vertical sliding strip per thread; rows processed in PAIRS:
//     two outputs share the 4-common-row column work (R5's verified median2)
//   * ring of 6 sorted rows; doubly-sorted-matrix pruning -> rank-7 of 13
//   * x4096 fp32 pre-scale avoids fp16 denormals; /4096 on output (exact pow2)
// ---------------------------------------------------------------------------

typedef __half2 h2;

__device__ __forceinline__ void cex(h2& a, h2& b) {
    h2 mn = __hmin2(a, b);
    b = __hmax2(a, b);
    a = mn;
}

// full sort of 4 (5 CE)
__device__ __forceinline__ void sort4(h2& a, h2& b, h2& c, h2& d) {
    cex(a, b); cex(c, d); cex(a, c); cex(b, d); cex(b, c);
}

// symmetric reflect for pad<=2:  -1->0, -2->1, N->N-1, N+1->N-2
__device__ __forceinline__ int refl(int i, int n) {
    i = (i < 0) ? (-1 - i) : i;
    i = (i >= n) ? (2 * n - 1 - i) : i;
    return i;
}

constexpr int IMG_H   = 512;
constexpr int IMG_W   = 512;
constexpr int PLANES  = 16 * 3;           // 48
constexpr int PAIRS   = PLANES / 2;       // 24 packed plane-pairs
constexpr int TROWS   = 16;               // output rows per thread
constexpr int STRIPS  = IMG_H / TROWS;    // 32
constexpr int PSTRIDE = IMG_H * IMG_W;

constexpr float SCALE     = 4096.0f;
constexpr float INV_SCALE = 1.0f / 4096.0f;

__device__ __forceinline__ void load_raw(const float* __restrict__ row,
                                         int xm2, int xm1, int x, int xp1, int xp2,
                                         float a[5], float b[5]) {
    a[0] = __ldg(row + xm2); a[1] = __ldg(row + xm1); a[2] = __ldg(row + x);
    a[3] = __ldg(row + xp1); a[4] = __ldg(row + xp2);
    const float* rb = row + PSTRIDE;
    b[0] = __ldg(rb + xm2); b[1] = __ldg(rb + xm1); b[2] = __ldg(rb + x);
    b[3] = __ldg(rb + xp1); b[4] = __ldg(rb + xp2);
}

// scale + pack + optimal 9-CE sort5
__device__ __forceinline__ void cvt_sort(const float a[5], const float b[5], h2 o[5]) {
    #pragma unroll
    for (int k = 0; k < 5; k++)
        o[k] = __floats2half2_rn(a[k] * SCALE, b[k] * SCALE);
    cex(o[0], o[1]); cex(o[3], o[4]); cex(o[2], o[4]); cex(o[2], o[3]);
    cex(o[0], o[3]); cex(o[0], o[2]); cex(o[1], o[4]); cex(o[1], o[3]); cex(o[1], o[2]);
}

// rank-7 of the 13 pruned candidates (verified R4/R5/R6/R7)
__device__ __forceinline__ h2 sel13(h2 a3, h2 a4, h2 b2, h2 b3, h2 b4,
                                    h2 c1, h2 c2, h2 c3,
                                    h2 d0, h2 d1, h2 d2, h2 e0, h2 e1) {
    // U = merge((d0,e0),(c1,d1,e1)) -> sorted 5
    h2 s0 = __hmin2(d0, c1), t0 = __hmax2(d0, c1);
    h2 v1 = __hmin2(t0, e1), v2 = __hmax2(t0, e1);
    h2 w0 = __hmin2(e0, d1), w1 = __hmax2(e0, d1);
    h2 U0 = s0;
    h2 U1 = __hmin2(v1, w0), U2 = __hmax2(v1, w0);
    h2 U3 = __hmin2(v2, w1), U4 = __hmax2(v2, w1);

    // V = merge((a3,b3,c3),(a4,b4)) -> sorted 5
    h2 m0 = __hmin2(a3, a4), h0 = __hmax2(a3, a4);
    h2 o1 = __hmin2(h0, c3), o2 = __hmax2(h0, c3);
    h2 p0 = __hmin2(b3, b4), p1 = __hmax2(b3, b4);
    h2 V0 = m0;
    h2 V1 = __hmin2(o1, p0), V2 = __hmax2(o1, p0);
    h2 V3 = __hmin2(o2, p1), V4 = __hmax2(o2, p1);

    // W = merge(U(5), (b2,c2,d2)) -> sorted 8, lanes W1..W6 only
    h2 hh  = __hmax2(U0, b2);
    h2 oo1 = __hmin2(hh, U4), oo2 = __hmax2(hh, U4);
    h2 qq0 = __hmin2(U2, d2), qq1 = __hmax2(U2, d2);
    h2 O1 = __hmin2(oo1, qq0), O2 = __hmax2(oo1, qq0);
    h2 O3 = __hmin2(oo2, qq1);
    h2 m2 = __hmin2(U1, c2), h2v = __hmax2(U1, c2);
    h2 E0 = m2;
    h2 E1 = __hmin2(h2v, U3), E2 = __hmax2(h2v, U3);
    h2 W1 = __hmin2(O1, E0), W2 = __hmax2(O1, E0);
    h2 W3 = __hmin2(O2, E1), W4 = __hmax2(O2, E1);
    h2 W5 = __hmin2(O3, E2), W6 = __hmax2(O3, E2);

    // rank-7 of union(W sorted 8, V sorted 5)
    h2 med = W6;
    med = __hmin2(med, __hmax2(W1, V4));
    med = __hmin2(med, __hmax2(W2, V3));
    med = __hmin2(med, __hmax2(W3, V2));
    med = __hmin2(med, __hmax2(W4, V1));
    med = __hmin2(med, __hmax2(W5, V0));
    return med;
}

// Two medians (consecutive output rows) from 6 sorted rows R0..R5.
// Window A = R0..R4, window B = R1..R5; common rows R1..R4 sorted once per
// column with only the required rank set. Bit-exact verified in R5.
__device__ __forceinline__ void median2(
    const h2 (&R0)[5], const h2 (&R1)[5], const h2 (&R2)[5],
    const h2 (&R3)[5], const h2 (&R4)[5], const h2 (&R5)[5],
    h2& medA, h2& medB)
{
    // ---- j=0: ranks 3,4 (common top-2) ----
    h2 a3A, a4A, a3B, a4B;
    {
        h2 p = R1[0], q = R2[0], rr = R3[0], ss = R4[0];
        h2 h1 = __hmax2(p, q), l1 = __hmin2(p, q);
        h2 hB = __hmax2(rr, ss), lB = __hmin2(rr, ss);
        h2 s3 = __hmax2(h1, hB);
        h2 s2 = __hmax2(__hmin2(h1, hB), __hmax2(l1, lB));
        h2 eA = R0[0], eB = R5[0];
        a4A = __hmax2(eA, s3); a3A = __hmax2(__hmin2(eA, s3), s2);
        a4B = __hmax2(eB, s3); a3B = __hmax2(__hmin2(eB, s3), s2);
    }
    // ---- j=4: ranks 0,1 (common bottom-2) ----
    h2 e0A, e1A, e0B, e1B;
    {
        h2 p = R1[4], q = R2[4], rr = R3[4], ss = R4[4];
        h2 h1 = __hmax2(p, q), l1 = __hmin2(p, q);
        h2 hB = __hmax2(rr, ss), lB = __hmin2(rr, ss);
        h2 s0 = __hmin2(l1, lB);
        h2 s1 = __hmin2(__hmax2(l1, lB), __hmin2(h1, hB));
        h2 eA = R0[4], eB = R5[4];
        e0A = __hmin2(eA, s0); e1A = __hmin2(__hmax2(eA, s0), s1);
        e0B = __hmin2(eB, s0); e1B = __hmin2(__hmax2(eB, s0), s1);
    }
    // ---- j=1: ranks 2,3,4 (common top-3: s1<=s2<=s3) ----
    h2 b2A, b3A, b4A, b2B, b3B, b4B;
    {
        h2 a = R1[1], b = R2[1], c = R3[1], d = R4[1];
        cex(a, b); cex(c, d);
        h2 s3 = __hmax2(b, d), bm = __hmin2(b, d), cm = __hmax2(a, c);
        h2 s1 = __hmin2(bm, cm), s2 = __hmax2(bm, cm);
        h2 eA = R0[1], eB = R5[1];
        {
            h2 m = __hmin2(eA, s3); b4A = __hmax2(eA, s3);
            b3A = __hmax2(m, s2); h2 m2 = __hmin2(m, s2);
            b2A = __hmax2(m2, s1);
        }
        {
            h2 m = __hmin2(eB, s3); b4B = __hmax2(eB, s3);
            b3B = __hmax2(m, s2); h2 m2 = __hmin2(m, s2);
            b2B = __hmax2(m2, s1);
        }
    }
    // ---- j=3: ranks 0,1,2 (common bottom-3: s0<=s1<=s2) ----
    h2 d0A, d1A, d2A, d0B, d1B, d2B;
    {
        h2 a = R1[3], b = R2[3], c = R3[3], d = R4[3];
        cex(a, b); cex(c, d);
        h2 s0 = __hmin2(a, c), cm = __hmax2(a, c), bm = __hmin2(b, d);
        h2 s1 = __hmin2(cm, bm), s2 = __hmax2(cm, bm);
        h2 eA = R0[3], eB = R5[3];
        {
            h2 m = __hmax2(eA, s0); d0A = __hmin2(eA, s0);
            d1A = __hmin2(m, s1); h2 m2 = __hmax2(m, s1);
            d2A = __hmin2(m2, s2);
        }
        {
            h2 m = __hmax2(eB, s0); d0B = __hmin2(eB, s0);
            d1B = __hmin2(m, s1); h2 m2 = __hmax2(m, s1);
            d2B = __hmin2(m2, s2);
        }
    }
    // ---- j=2: ranks 1,2,3 (full common sort4 + insert chains) ----
    h2 c1A, c2A, c3A, c1B, c2B, c3B;
    {
        h2 a = R1[2], b = R2[2], c = R3[2], d = R4[2];
        sort4(a, b, c, d);
        h2 eA = R0[2], eB = R5[2];
        {
            h2 u = __hmax2(eA, a);
            c1A = __hmin2(u, b); u = __hmax2(u, b);
            c2A = __hmin2(u, c); u = __hmax2(u, c);
            c3A = __hmin2(u, d);
        }
        {
            h2 u = __hmax2(eB, a);
            c1B = __hmin2(u, b); u = __hmax2(u, b);
            c2B = __hmin2(u, c); u = __hmax2(u, c);
            c3B = __hmin2(u, d);
        }
    }
    medA = sel13(a3A, a4A, b2A, b3A, b4A, c1A, c2A, c3A, d0A, d1A, d2A, e0A, e1A);
    medB = sel13(a3B, a4B, b2B, b3B, b4B, c1B, c2B, c3B, d0B, d1B, d2B, e0B, e1B);
}

__global__ void __launch_bounds__(128, 6)
median5x5_kernel(const float* __restrict__ src, float* __restrict__ dst) {
    const int tid   = blockIdx.x * blockDim.x + threadIdx.x;
    const int x     = tid & (IMG_W - 1);
    const int rest  = tid >> 9;                 // / 512
    const int strip = rest & (STRIPS - 1);      // % 32
    const int pair  = rest >> 5;                // / 32
    if (pair >= PAIRS) return;

    const float* sA = src + (size_t)(2 * pair) * PSTRIDE;
    float*       dA = dst + (size_t)(2 * pair) * PSTRIDE;

    const int xm2 = refl(x - 2, IMG_W);
    const int xm1 = refl(x - 1, IMG_W);
    const int xp1 = refl(x + 1, IMG_W);
    const int xp2 = refl(x + 2, IMG_W);
    const int y0  = strip * TROWS;

    // Ring of 6 sorted rows. Relative row i (abs y0-2+i) lives in slot i%6.
    h2 r[6][5];

    #pragma unroll
    for (int i = 0; i < 4; i++) {               // rel rows 0..3 (abs y0-2..y0+1)
        float a[5], b[5];
        const int yy = refl(y0 - 2 + i, IMG_H);
        load_raw(sA + yy * IMG_W, xm2, xm1, x, xp1, xp2, a, b);
        cvt_sort(a, b, r[i]);
    }

    #pragma unroll
    for (int tp = 0; tp < TROWS / 2; tp++) {
        // load + sort the two new rows (rel 2tp+4, 2tp+5; abs y0+2tp+2, +3)
        {
            float a0[5], b0[5], a1[5], b1[5];
            const int yyA = refl(y0 + 2 * tp + 2, IMG_H);
            const int yyB = refl(y0 + 2 * tp + 3, IMG_H);
            load_raw(sA + yyA * IMG_W, xm2, xm1, x, xp1, xp2, a0, b0);
            load_raw(sA + yyB * IMG_W, xm2, xm1, x, xp1, xp2, a1, b1);
            cvt_sort(a0, b0, r[(2 * tp + 4) % 6]);
            cvt_sort(a1, b1, r[(2 * tp + 5) % 6]);
        }

        h2 medA, medB;
        median2(r[(2 * tp + 0) % 6], r[(2 * tp + 1) % 6], r[(2 * tp + 2) % 6],
                r[(2 * tp + 3) % 6], r[(2 * tp + 4) % 6], r[(2 * tp + 5) % 6],
                medA, medB);

        const int yA = y0 + 2 * tp;
        dA[yA * IMG_W + x]                 = __low2float(medA)  * INV_SCALE;
        dA[yA * IMG_W + x + PSTRIDE]       = __high2float(medA) * INV_SCALE;
        dA[(yA + 1) * IMG_W + x]           = __low2float(medB)  * INV_SCALE;
        dA[(yA + 1) * IMG_W + x + PSTRIDE] = __high2float(medB) * INV_SCALE;
    }
}

extern "C" void kernel_launch(void* const* d_in, const int* in_sizes, int n_in,
                              void* d_out, int out_size) {
    (void)in_sizes; (void)n_in; (void)out_size;
    const float* src = (const float*)d_in[0];
    float*       dst = (float*)d_out;

    const int total_threads = PAIRS * IMG_W * STRIPS;   // 393216
    const int block = 128;
    const int grid  = total_threads / block;            // 3072
    median5x5_kernel<<<grid, block>>>(src, dst);
}